// round 13
// baseline (speedup 1.0000x reference)
#include <cuda_runtime.h>
#include <cuda_fp16.h>
#include <mma.h>
using namespace nvcuda;

#define N_NODES 50000
#define N_EDGES 800000
#define HID 128
#define N_GRAPHS 64
#define CAP 64          // padded CSR bucket capacity (P(deg>=64) ~ 1e-18)
#define FULL 0xffffffffu

// ---------------- scratch (static device globals; no allocation) ----------
__device__ float  g_bufB[(N_NODES + 64) * HID];  // h2 raw (fp32), row-padded
__device__ __half g_hs[(N_NODES + 1) * HID];     // dinv_i*h1_i (fp16) + zero row
__device__ __half g_hA[(N_NODES + 64) * HID];    // aggregated h1 (fp16), padded
__device__ __half g_W2h[HID * HID];              // W2 hi (fp16)
__device__ __half g_W2l[HID * HID];              // W2 residual (fp16)
__device__ float  g_xs[(N_NODES + 1) * 16];      // dinv_i*x_i + zero row
__device__ float  g_xa[N_NODES * 16];            // aggregated, di-scaled x
__device__ int    g_cur[N_NODES];                // in-degree (atomic bump)
__device__ int    g_csr[N_NODES * CAP];          // padded buckets of source ids
__device__ float  g_dinv[N_NODES];
__device__ float  g_pool[N_GRAPHS * HID];
__device__ int    g_gcnt[N_GRAPHS];
__device__ int    g_is64;

// ---------------- helpers ---------------------------------------------------
__device__ __forceinline__ int ld_idx(const void* p, long long i, int is64) {
    if (is64) return (int)((const long long*)p)[i];
    return ((const int*)p)[i];
}

__device__ __forceinline__ float4 h4_to_f4(unsigned int a, unsigned int b) {
    float2 p = __half22float2(*(const __half2*)&a);
    float2 q = __half22float2(*(const __half2*)&b);
    return make_float4(p.x, p.y, q.x, q.y);
}

// local int64/int32 detection from the first 64 index values (deterministic)
__device__ __forceinline__ int detect64(const void* ei, int tid, int* s_flag) {
    if (tid == 0) *s_flag = 1;
    __syncthreads();
    if (tid < 64) {
        long long v = ((const long long*)ei)[tid];
        if (v < 0 || v >= N_NODES) *s_flag = 0;
    }
    __syncthreads();
    return *s_flag;
}

// ---------------- kernels ---------------------------------------------------
__global__ void k_init() {
    int i = blockIdx.x * blockDim.x + threadIdx.x;
    if (i < N_NODES) g_cur[i] = 0;
    if (i < 16) g_xs[N_NODES * 16 + i] = 0.f;           // zero sentinel row
    if (i < HID) g_hs[N_NODES * HID + i] = __float2half(0.f);
}

// W2 split to fp16 hi/lo + zero pool/gcnt (independent of CSR build)
__global__ void k_w2z(const float* __restrict__ W2) {
    int t = blockIdx.x * blockDim.x + threadIdx.x;
    if (t < HID * HID) {
        float w = W2[t];
        __half h = __float2half_rn(w);
        g_W2h[t] = h;
        g_W2l[t] = __float2half_rn(w - __half2float(h));
    }
    if (t < N_GRAPHS * HID) g_pool[t] = 0.f;
    if (t < N_GRAPHS) g_gcnt[t] = 0;
}

// per-graph node counts (dtype detected from ei — same dtype as batch)
__global__ void k_gcnt(const void* ei, const void* batch) {
    __shared__ int s_is64;
    int tid = threadIdx.x;
    int is64 = detect64(ei, tid, &s_is64);
    int n = blockIdx.x * blockDim.x + tid;
    if (n < N_NODES) {
        int g = ld_idx(batch, n, is64);
        atomicAdd(&g_gcnt[g], 1);
    }
}

// single-pass padded-bucket CSR build; 2 edges per thread (16B index loads)
__global__ void k_build(const void* ei) {
    __shared__ int s_is64;
    int tid = threadIdx.x;
    int is64 = detect64(ei, tid, &s_is64);
    int t = blockIdx.x * blockDim.x + tid;
    if (2 * t < N_EDGES) {
        int s0, s1, d0, d1;
        if (is64) {
            longlong2 sv = ((const longlong2*)ei)[t];
            longlong2 dv = ((const longlong2*)((const long long*)ei + N_EDGES))[t];
            s0 = (int)sv.x; s1 = (int)sv.y;
            d0 = (int)dv.x; d1 = (int)dv.y;
        } else {
            int2 sv = ((const int2*)ei)[t];
            int2 dv = ((const int2*)((const int*)ei + N_EDGES))[t];
            s0 = sv.x; s1 = sv.y;
            d0 = dv.x; d1 = dv.y;
        }
        int p0 = atomicAdd(&g_cur[d0], 1);
        if (p0 < CAP) g_csr[d0 * CAP + p0] = s0;
        int p1 = atomicAdd(&g_cur[d1], 1);
        if (p1 < CAP) g_csr[d1 * CAP + p1] = s1;
    }
    if (blockIdx.x == 0 && tid == 0) g_is64 = is64;
}

// dinv + pre-scaled features xs = dinv_i * x_i
__global__ void k_dinvxs(const float* __restrict__ x) {
    int t = blockIdx.x * blockDim.x + threadIdx.x;
    int i = t >> 4;                 // node
    int col = t & 15;
    if (i >= N_NODES) return;
    float di = rsqrtf((float)(g_cur[i] + 1));   // +1 self-loop
    if (col == 0) g_dinv[i] = di;
    g_xs[i * 16 + col] = x[i * 16 + col] * di;
}

// Pure gather for layer 1: xa_i = di*(xs[i] + sum_e xs[s]).
// One warp per node; indices loaded ONCE per bucket, distributed via shfl
// (no per-round csr latency in the chain); 16 edges / iteration in flight.
__global__ void k_aggx() {
    int i = (blockIdx.x * blockDim.x + threadIdx.x) >> 5;
    if (i >= N_NODES) return;
    int lane = threadIdx.x & 31;
    int grp = lane >> 2;    // 0..7 edge group
    int sub = lane & 3;     // float4 slot within 16-float row
    float di = g_dinv[i];
    const float4* xs4 = (const float4*)g_xs;

    int base = i * CAP;
    int deg = min(g_cur[i], CAP);
    int idxs  = g_csr[base + lane];                       // slots 0..31
    int idxs2 = (deg > 32) ? g_csr[base + 32 + lane] : 0; // slots 32..63

    float4 acc0 = (grp == 0) ? xs4[i * 4 + sub]
                             : make_float4(0.f, 0.f, 0.f, 0.f);  // self term
    float4 acc1 = make_float4(0.f, 0.f, 0.f, 0.f);
    for (int e = 0; e < deg; e += 16) {
        int t0 = e + grp;
        int t1 = e + 8 + grp;
        int a0 = __shfl_sync(FULL, idxs,  t0 & 31);
        int b0 = __shfl_sync(FULL, idxs2, t0 & 31);
        int a1 = __shfl_sync(FULL, idxs,  t1 & 31);
        int b1 = __shfl_sync(FULL, idxs2, t1 & 31);
        int s0 = (t0 < deg) ? ((t0 < 32) ? a0 : b0) : N_NODES;
        int s1 = (t1 < deg) ? ((t1 < 32) ? a1 : b1) : N_NODES;
        float4 v0 = xs4[s0 * 4 + sub];
        float4 v1 = xs4[s1 * 4 + sub];
        acc0.x += v0.x; acc0.y += v0.y; acc0.z += v0.z; acc0.w += v0.w;
        acc1.x += v1.x; acc1.y += v1.y; acc1.z += v1.z; acc1.w += v1.w;
    }
    float4 acc = make_float4(acc0.x + acc1.x, acc0.y + acc1.y,
                             acc0.z + acc1.z, acc0.w + acc1.w);
    #pragma unroll
    for (int off = 4; off < 32; off <<= 1) {
        acc.x += __shfl_xor_sync(FULL, acc.x, off);
        acc.y += __shfl_xor_sync(FULL, acc.y, off);
        acc.z += __shfl_xor_sync(FULL, acc.z, off);
        acc.w += __shfl_xor_sync(FULL, acc.w, off);
    }
    if (grp == 0) {
        acc.x *= di; acc.y *= di; acc.z *= di; acc.w *= di;
        ((float4*)g_xa)[i * 4 + sub] = acc;
    }
}

// Tiled layer-1 GEMM: hs = di * relu(xa @ W1 + b1), fp16 out.
// 32 rows/block, 128 threads (one output col each).
__global__ void __launch_bounds__(128) k_gemm1(const float* __restrict__ W1,
                                               const float* __restrict__ b1) {
    __shared__ float W1s[16 * 128];
    __shared__ float xas[32 * 16];
    __shared__ float dis[32];
    int tid = threadIdx.x;
    int row0 = blockIdx.x * 32;
    {
        float4* d4 = (float4*)W1s;
        const float4* s4 = (const float4*)W1;
        #pragma unroll
        for (int j = 0; j < 4; j++) d4[tid + 128 * j] = s4[tid + 128 * j];
    }
    {
        float4* d4 = (float4*)xas;
        const float4* s4 = (const float4*)g_xa;
        int r = row0 * 4 + tid;
        d4[tid] = (r < N_NODES * 4) ? s4[r] : make_float4(0.f, 0.f, 0.f, 0.f);
    }
    if (tid < 32) {
        int r = row0 + tid;
        dis[tid] = (r < N_NODES) ? g_dinv[r] : 0.f;
    }
    __syncthreads();

    float w[16];
    #pragma unroll
    for (int k = 0; k < 16; k++) w[k] = W1s[k * 128 + tid];
    float bias = b1[tid];
    int rmax = min(32, N_NODES - row0);
    for (int r = 0; r < rmax; r++) {
        float acc = bias;
        #pragma unroll
        for (int k = 0; k < 16; k++) acc = fmaf(xas[r * 16 + k], w[k], acc);
        float hsv = fmaxf(acc, 0.f) * dis[r];       // hs = di * relu(h1)
        g_hs[(row0 + r) * 128 + tid] = __float2half(hsv);
    }
}

// Aggregate hs (fp16): hA_i = di * (hs[i] + sum_e hs[s]), fp16 out.
// Bucket indices via single load + shfl; 8 edges / iteration in flight.
__global__ void k_aggh() {
    int i = (blockIdx.x * blockDim.x + threadIdx.x) >> 5;
    if (i >= N_NODES) return;
    int lane = threadIdx.x & 31;
    int grp = lane >> 4;    // 0..1
    int sub = lane & 15;    // uint4 slot within 128-half row
    float di = g_dinv[i];
    const uint4* __restrict__ h = (const uint4*)g_hs;

    int base = i * CAP;
    int deg = min(g_cur[i], CAP);
    int idxs  = g_csr[base + lane];
    int idxs2 = (deg > 32) ? g_csr[base + 32 + lane] : 0;

    float4 a0, a1;
    if (grp == 0) {         // self term
        uint4 sv = h[i * 16 + sub];
        a0 = h4_to_f4(sv.x, sv.y);
        a1 = h4_to_f4(sv.z, sv.w);
    } else {
        a0 = make_float4(0.f, 0.f, 0.f, 0.f);
        a1 = make_float4(0.f, 0.f, 0.f, 0.f);
    }

    for (int e = 0; e < deg; e += 8) {
        int t0 = e + grp, t1 = e + grp + 2, t2 = e + grp + 4, t3 = e + grp + 6;
        int p0 = __shfl_sync(FULL, idxs,  t0 & 31);
        int q0 = __shfl_sync(FULL, idxs2, t0 & 31);
        int p1 = __shfl_sync(FULL, idxs,  t1 & 31);
        int q1 = __shfl_sync(FULL, idxs2, t1 & 31);
        int p2 = __shfl_sync(FULL, idxs,  t2 & 31);
        int q2 = __shfl_sync(FULL, idxs2, t2 & 31);
        int p3 = __shfl_sync(FULL, idxs,  t3 & 31);
        int q3 = __shfl_sync(FULL, idxs2, t3 & 31);
        int s0 = (t0 < deg) ? ((t0 < 32) ? p0 : q0) : N_NODES;
        int s1 = (t1 < deg) ? ((t1 < 32) ? p1 : q1) : N_NODES;
        int s2 = (t2 < deg) ? ((t2 < 32) ? p2 : q2) : N_NODES;
        int s3 = (t3 < deg) ? ((t3 < 32) ? p3 : q3) : N_NODES;
        uint4 v0 = h[s0 * 16 + sub];
        uint4 v1 = h[s1 * 16 + sub];
        uint4 v2 = h[s2 * 16 + sub];
        uint4 v3 = h[s3 * 16 + sub];
        float4 f00 = h4_to_f4(v0.x, v0.y), f01 = h4_to_f4(v0.z, v0.w);
        float4 f10 = h4_to_f4(v1.x, v1.y), f11 = h4_to_f4(v1.z, v1.w);
        float4 f20 = h4_to_f4(v2.x, v2.y), f21 = h4_to_f4(v2.z, v2.w);
        float4 f30 = h4_to_f4(v3.x, v3.y), f31 = h4_to_f4(v3.z, v3.w);
        a0.x += (f00.x + f10.x) + (f20.x + f30.x);
        a0.y += (f00.y + f10.y) + (f20.y + f30.y);
        a0.z += (f00.z + f10.z) + (f20.z + f30.z);
        a0.w += (f00.w + f10.w) + (f20.w + f30.w);
        a1.x += (f01.x + f11.x) + (f21.x + f31.x);
        a1.y += (f01.y + f11.y) + (f21.y + f31.y);
        a1.z += (f01.z + f11.z) + (f21.z + f31.z);
        a1.w += (f01.w + f11.w) + (f21.w + f31.w);
    }
    // combine the 2 groups
    a0.x += __shfl_xor_sync(FULL, a0.x, 16);
    a0.y += __shfl_xor_sync(FULL, a0.y, 16);
    a0.z += __shfl_xor_sync(FULL, a0.z, 16);
    a0.w += __shfl_xor_sync(FULL, a0.w, 16);
    a1.x += __shfl_xor_sync(FULL, a1.x, 16);
    a1.y += __shfl_xor_sync(FULL, a1.y, 16);
    a1.z += __shfl_xor_sync(FULL, a1.z, 16);
    a1.w += __shfl_xor_sync(FULL, a1.w, 16);

    float4 v = (grp == 0) ? a0 : a1;
    v.x *= di; v.y *= di; v.z *= di; v.w *= di;
    __half2 lo = __floats2half2_rn(v.x, v.y);
    __half2 hi = __floats2half2_rn(v.z, v.w);
    uint2 pk;
    pk.x = *(const unsigned int*)&lo;
    pk.y = *(const unsigned int*)&hi;
    ((uint2*)g_hA)[i * 32 + 2 * sub + grp] = pk;
}

// h2raw = hA @ (W2h + W2l) -> g_bufB via tensor cores; bias+relu folded
// into k_pool. Direct fragment stores to global (row-padded) — no smem.
__global__ void __launch_bounds__(256) k_gemm2w() {
    int tid = threadIdx.x;
    int wid = tid >> 5;
    int wr = wid >> 1;          // 0..3 warp row
    int wc = wid & 1;           // 0..1 warp col
    int row0 = blockIdx.x * 64;

    wmma::fragment<wmma::accumulator, 16, 16, 16, float> acc[4];
    #pragma unroll
    for (int c = 0; c < 4; c++) wmma::fill_fragment(acc[c], 0.f);

    const __half* A = g_hA + (row0 + wr * 16) * HID;
    for (int k = 0; k < HID; k += 16) {
        wmma::fragment<wmma::matrix_a, 16, 16, 16, __half, wmma::row_major> a;
        wmma::load_matrix_sync(a, A + k, HID);
        #pragma unroll
        for (int c = 0; c < 4; c++) {
            int col = wc * 64 + c * 16;
            wmma::fragment<wmma::matrix_b, 16, 16, 16, __half, wmma::row_major> b;
            wmma::load_matrix_sync(b, g_W2h + k * HID + col, HID);
            wmma::mma_sync(acc[c], a, b, acc[c]);
            wmma::load_matrix_sync(b, g_W2l + k * HID + col, HID);
            wmma::mma_sync(acc[c], a, b, acc[c]);
        }
    }
    float* C = g_bufB + (row0 + wr * 16) * HID;
    #pragma unroll
    for (int c = 0; c < 4; c++)
        wmma::store_matrix_sync(C + wc * 64 + c * 16, acc[c], HID,
                                wmma::mem_row_major);
}

// pool sums of relu(h2raw + b2); batch sorted -> local accumulation.
__global__ void k_pool(const void* batch, const float* __restrict__ b2) {
    int tid = threadIdx.x;
    int start = blockIdx.x * 32;
    int end = min(start + 32, N_NODES);
    if (start >= N_NODES) return;
    int is64 = g_is64;
    float bias = b2[tid];
    int curg = ld_idx(batch, start, is64);
    float acc = 0.f;
    for (int n = start; n < end; n++) {
        int g = ld_idx(batch, n, is64);
        if (g != curg) {
            atomicAdd(&g_pool[curg * 128 + tid], acc);
            acc = 0.f;
            curg = g;
        }
        acc += fmaxf(g_bufB[n * 128 + tid] + bias, 0.f);
    }
    atomicAdd(&g_pool[curg * 128 + tid], acc);
}

__global__ void k_final(const float* __restrict__ Wfc,
                        const float* __restrict__ bfc,
                        float* __restrict__ out) {
    int tid = threadIdx.x;   // 1024 = 64*16
    int g = tid >> 4;
    int o = tid & 15;
    float c = (float)max(g_gcnt[g], 1);
    float s = 0.f;
    #pragma unroll 8
    for (int k = 0; k < 128; k++)
        s = fmaf(g_pool[g * 128 + k], Wfc[k * 16 + o], s);
    out[tid] = s / c + bfc[o];
}

// ---------------- launch ----------------------------------------------------
extern "C" void kernel_launch(void* const* d_in, const int* in_sizes, int n_in,
                              void* d_out, int out_size) {
    const float* x   = (const float*)d_in[0];
    const void*  ei  = d_in[1];
    const void*  bat = d_in[2];
    const float* W1  = (const float*)d_in[3];
    const float* b1  = (const float*)d_in[4];
    const float* W2  = (const float*)d_in[5];
    const float* b2  = (const float*)d_in[6];
    const float* Wfc = (const float*)d_in[7];
    const float* bfc = (const float*)d_in[8];
    float* out = (float*)d_out;

    k_init<<<(N_NODES + 255) / 256, 256>>>();                 // 1
    k_w2z<<<(HID * HID + 255) / 256, 256>>>(W2);              // 2
    k_gcnt<<<(N_NODES + 255) / 256, 256>>>(ei, bat);          // 3
    k_build<<<(N_EDGES / 2 + 255) / 256, 256>>>(ei);          // 4  <- ncu slot
    k_dinvxs<<<(N_NODES * 16 + 255) / 256, 256>>>(x);         // 5
    k_aggx<<<(N_NODES * 32 + 255) / 256, 256>>>();            // 6
    k_gemm1<<<(N_NODES + 31) / 32, 128>>>(W1, b1);            // 7
    k_aggh<<<(N_NODES + 7) / 8, 256>>>();                     // 8
    k_gemm2w<<<(N_NODES + 63) / 64, 256>>>();                 // 9
    k_pool<<<(N_NODES + 31) / 32, 128>>>(bat, b2);            // 10
    k_final<<<1, 1024>>>(Wfc, bfc, out);                      // 11
}

// round 14
// speedup vs baseline: 1.4679x; 1.4679x over previous
#include <cuda_runtime.h>
#include <cuda_fp16.h>

#define N_NODES 50000
#define N_EDGES 800000
#define HID 128
#define N_GRAPHS 64
#define CAP 64          // padded CSR bucket capacity (P(deg>=64) ~ 1e-18)
#define FULL 0xffffffffu

// ---------------- scratch (static device globals; no allocation) ----------
__device__ float  g_bufA[N_NODES * HID];       // aggregated h1 (fp32)
__device__ float  g_bufB[N_NODES * HID];       // h2 (fp32)
__device__ __half g_hs[(N_NODES + 1) * HID];   // dinv_i*h1_i (fp16) + zero row
__device__ float  g_xs[(N_NODES + 1) * 16];    // dinv_i*x_i + zero row
__device__ float  g_xa[N_NODES * 16];          // aggregated, di-scaled x
__device__ int    g_cur[N_NODES];              // in-degree (atomic bump)
__device__ int    g_csr[N_NODES * CAP];        // padded buckets of source ids
__device__ float  g_dinv[N_NODES];
__device__ float  g_pool[N_GRAPHS * HID];
__device__ int    g_gcnt[N_GRAPHS];
__device__ int    g_is64;

// ---------------- helpers ---------------------------------------------------
__device__ __forceinline__ int ld_idx(const void* p, long long i, int is64) {
    if (is64) return (int)((const long long*)p)[i];
    return ((const int*)p)[i];
}

__device__ __forceinline__ void fma2(unsigned long long& d,
                                     unsigned long long a,
                                     unsigned long long b) {
    asm("fma.rn.f32x2 %0, %1, %2, %3;" : "=l"(d) : "l"(a), "l"(b), "l"(d));
}
__device__ __forceinline__ unsigned long long pack2(float x, float y) {
    unsigned long long r;
    asm("mov.b64 %0, {%1, %2};" : "=l"(r) : "f"(x), "f"(y));
    return r;
}
__device__ __forceinline__ void unpack2(unsigned long long v, float& x, float& y) {
    asm("mov.b64 {%0, %1}, %2;" : "=f"(x), "=f"(y) : "l"(v));
}

__device__ __forceinline__ float4 h4_to_f4(unsigned int a, unsigned int b) {
    float2 p = __half22float2(*(const __half2*)&a);
    float2 q = __half22float2(*(const __half2*)&b);
    return make_float4(p.x, p.y, q.x, q.y);
}

// local int64/int32 detection from the first 64 index values (deterministic)
__device__ __forceinline__ int detect64(const void* ei, int tid, int* s_flag) {
    if (tid == 0) *s_flag = 1;
    __syncthreads();
    if (tid < 64) {
        long long v = ((const long long*)ei)[tid];
        if (v < 0 || v >= N_NODES) *s_flag = 0;
    }
    __syncthreads();
    return *s_flag;
}

// ---------------- kernels ---------------------------------------------------
__global__ void k_init() {
    int i = blockIdx.x * blockDim.x + threadIdx.x;
    if (i < N_NODES) g_cur[i] = 0;
    if (i < N_GRAPHS * HID) g_pool[i] = 0.f;
    if (i < N_GRAPHS) g_gcnt[i] = 0;
    if (i < 16) g_xs[N_NODES * 16 + i] = 0.f;           // zero sentinel row
    if (i < HID) g_hs[N_NODES * HID + i] = __float2half(0.f);
}

// single-pass padded-bucket CSR build; 2 edges per thread (16B index loads)
__global__ void k_build(const void* ei) {
    __shared__ int s_is64;
    int tid = threadIdx.x;
    int is64 = detect64(ei, tid, &s_is64);
    int t = blockIdx.x * blockDim.x + tid;
    if (2 * t < N_EDGES) {
        int s0, s1, d0, d1;
        if (is64) {
            longlong2 sv = ((const longlong2*)ei)[t];
            longlong2 dv = ((const longlong2*)((const long long*)ei + N_EDGES))[t];
            s0 = (int)sv.x; s1 = (int)sv.y;
            d0 = (int)dv.x; d1 = (int)dv.y;
        } else {
            int2 sv = ((const int2*)ei)[t];
            int2 dv = ((const int2*)((const int*)ei + N_EDGES))[t];
            s0 = sv.x; s1 = sv.y;
            d0 = dv.x; d1 = dv.y;
        }
        int p0 = atomicAdd(&g_cur[d0], 1);
        if (p0 < CAP) g_csr[d0 * CAP + p0] = s0;
        int p1 = atomicAdd(&g_cur[d1], 1);
        if (p1 < CAP) g_csr[d1 * CAP + p1] = s1;
    }
    if (blockIdx.x == 0 && tid == 0) g_is64 = is64;
}

// dinv + pre-scaled features xs = dinv_i * x_i
__global__ void k_dinvxs(const float* __restrict__ x) {
    int t = blockIdx.x * blockDim.x + threadIdx.x;
    int i = t >> 4;                 // node
    int col = t & 15;
    if (i >= N_NODES) return;
    float di = rsqrtf((float)(g_cur[i] + 1));   // +1 self-loop
    if (col == 0) g_dinv[i] = di;
    g_xs[i * 16 + col] = x[i * 16 + col] * di;
}

// Pure gather for layer 1: xa_i = di*(xs[i] + sum_e xs[s]).
// One warp per node; 8 edge-groups of 4 lanes, float4 per lane.
__global__ void k_aggx() {
    int i = (blockIdx.x * blockDim.x + threadIdx.x) >> 5;
    if (i >= N_NODES) return;
    int lane = threadIdx.x & 31;
    int grp = lane >> 2;    // 0..7 edge group
    int sub = lane & 3;     // float4 slot within 16-float row
    float di = g_dinv[i];
    const float4* xs4 = (const float4*)g_xs;

    float4 acc = (grp == 0) ? xs4[i * 4 + sub]
                            : make_float4(0.f, 0.f, 0.f, 0.f);   // self term
    int base = i * CAP;
    int deg = min(g_cur[i], CAP);
    for (int e = 0; e < deg; e += 8) {
        int idx = e + grp;
        int s = (idx < deg) ? g_csr[base + idx] : N_NODES;   // sentinel -> 0
        float4 v = xs4[s * 4 + sub];
        acc.x += v.x; acc.y += v.y; acc.z += v.z; acc.w += v.w;
    }
    #pragma unroll
    for (int off = 4; off < 32; off <<= 1) {
        acc.x += __shfl_xor_sync(FULL, acc.x, off);
        acc.y += __shfl_xor_sync(FULL, acc.y, off);
        acc.z += __shfl_xor_sync(FULL, acc.z, off);
        acc.w += __shfl_xor_sync(FULL, acc.w, off);
    }
    if (grp == 0) {
        acc.x *= di; acc.y *= di; acc.z *= di; acc.w *= di;
        ((float4*)g_xa)[i * 4 + sub] = acc;
    }
}

// Tiled layer-1 GEMM: hs = di * relu(xa @ W1 + b1), fp16 out.
// 32 rows/block, 128 threads (one output col each).
__global__ void __launch_bounds__(128) k_gemm1(const float* __restrict__ W1,
                                               const float* __restrict__ b1) {
    __shared__ float W1s[16 * 128];
    __shared__ float xas[32 * 16];
    __shared__ float dis[32];
    int tid = threadIdx.x;
    int row0 = blockIdx.x * 32;
    {
        float4* d4 = (float4*)W1s;
        const float4* s4 = (const float4*)W1;
        #pragma unroll
        for (int j = 0; j < 4; j++) d4[tid + 128 * j] = s4[tid + 128 * j];
    }
    {
        float4* d4 = (float4*)xas;
        const float4* s4 = (const float4*)g_xa;
        int r = row0 * 4 + tid;
        d4[tid] = (r < N_NODES * 4) ? s4[r] : make_float4(0.f, 0.f, 0.f, 0.f);
    }
    if (tid < 32) {
        int r = row0 + tid;
        dis[tid] = (r < N_NODES) ? g_dinv[r] : 0.f;
    }
    __syncthreads();

    float w[16];
    #pragma unroll
    for (int k = 0; k < 16; k++) w[k] = W1s[k * 128 + tid];
    float bias = b1[tid];
    int rmax = min(32, N_NODES - row0);
    for (int r = 0; r < rmax; r++) {
        float acc = bias;
        #pragma unroll
        for (int k = 0; k < 16; k++) acc = fmaf(xas[r * 16 + k], w[k], acc);
        float hsv = fmaxf(acc, 0.f) * dis[r];       // hs = di * relu(h1)
        g_hs[(row0 + r) * 128 + tid] = __float2half(hsv);
    }
}

// Aggregate hs (fp16): bufA_i = di * (hs[i] + sum_e hs[s]).
// One warp per node; 2 edge-groups of 16 lanes, uint4 (8 halves) per lane.
__global__ void k_aggh() {
    int i = (blockIdx.x * blockDim.x + threadIdx.x) >> 5;
    if (i >= N_NODES) return;
    int lane = threadIdx.x & 31;
    int grp = lane >> 4;    // 0..1
    int sub = lane & 15;    // uint4 slot within 128-half row
    float di = g_dinv[i];
    const uint4* __restrict__ h = (const uint4*)g_hs;

    float4 a0, a1;
    if (grp == 0) {         // self term
        uint4 sv = h[i * 16 + sub];
        a0 = h4_to_f4(sv.x, sv.y);
        a1 = h4_to_f4(sv.z, sv.w);
    } else {
        a0 = make_float4(0.f, 0.f, 0.f, 0.f);
        a1 = make_float4(0.f, 0.f, 0.f, 0.f);
    }

    int base = i * CAP;
    int deg = min(g_cur[i], CAP);
    for (int e = 0; e < deg; e += 4) {
        int i0 = e + grp;
        int i1 = e + grp + 2;
        int s0 = (i0 < deg) ? g_csr[base + i0] : N_NODES;
        int s1 = (i1 < deg) ? g_csr[base + i1] : N_NODES;
        uint4 v0 = h[s0 * 16 + sub];
        uint4 v1 = h[s1 * 16 + sub];
        float4 f00 = h4_to_f4(v0.x, v0.y);
        float4 f01 = h4_to_f4(v0.z, v0.w);
        float4 f10 = h4_to_f4(v1.x, v1.y);
        float4 f11 = h4_to_f4(v1.z, v1.w);
        a0.x += f00.x + f10.x; a0.y += f00.y + f10.y;
        a0.z += f00.z + f10.z; a0.w += f00.w + f10.w;
        a1.x += f01.x + f11.x; a1.y += f01.y + f11.y;
        a1.z += f01.z + f11.z; a1.w += f01.w + f11.w;
    }
    // combine the 2 groups
    a0.x += __shfl_xor_sync(FULL, a0.x, 16);
    a0.y += __shfl_xor_sync(FULL, a0.y, 16);
    a0.z += __shfl_xor_sync(FULL, a0.z, 16);
    a0.w += __shfl_xor_sync(FULL, a0.w, 16);
    a1.x += __shfl_xor_sync(FULL, a1.x, 16);
    a1.y += __shfl_xor_sync(FULL, a1.y, 16);
    a1.z += __shfl_xor_sync(FULL, a1.z, 16);
    a1.w += __shfl_xor_sync(FULL, a1.w, 16);

    a0.x *= di; a0.y *= di; a0.z *= di; a0.w *= di;
    a1.x *= di; a1.y *= di; a1.z *= di; a1.w *= di;
    float4* out4 = (float4*)g_bufA;
    out4[i * 32 + 2 * sub + grp] = (grp == 0) ? a0 : a1;
}

// h2 = relu(bufA @ W2 + b2) -> bufB.  BM=64, BN=128, BK=16, 256 threads.
// Inner loop in packed fp32x2.
__global__ void k_gemm2(const float* __restrict__ W2, const float* __restrict__ b2) {
    __shared__ float As[16][64];
    __shared__ float Bs[16][128];
    int tid = threadIdx.x;
    int tx = tid & 31;
    int ty = tid >> 5;
    int row0 = blockIdx.x * 64;
    unsigned long long acc2[4][4];
    #pragma unroll
    for (int q = 0; q < 4; q++)
        #pragma unroll
        for (int c = 0; c < 4; c++) acc2[q][c] = 0ull;

    const float* A = g_bufA;
    for (int k0 = 0; k0 < 128; k0 += 16) {
        {
            int r = tid >> 2;
            int kq = (tid & 3) * 4;
            int row = row0 + r;
            float4 v = make_float4(0.f, 0.f, 0.f, 0.f);
            if (row < N_NODES)
                v = ((const float4*)A)[(row * 128 + k0 + kq) >> 2];
            As[kq + 0][r] = v.x;
            As[kq + 1][r] = v.y;
            As[kq + 2][r] = v.z;
            As[kq + 3][r] = v.w;
        }
        {
            const float4* W4 = (const float4*)(W2 + k0 * 128);
            float4* Bs4 = (float4*)&Bs[0][0];
            Bs4[tid] = W4[tid];
            Bs4[tid + 256] = W4[tid + 256];
        }
        __syncthreads();
        #pragma unroll
        for (int k = 0; k < 16; k++) {
            float4 b = *((float4*)&Bs[k][tx * 4]);
            unsigned long long bb[4];
            bb[0] = pack2(b.x, b.x);
            bb[1] = pack2(b.y, b.y);
            bb[2] = pack2(b.z, b.z);
            bb[3] = pack2(b.w, b.w);
            #pragma unroll
            for (int q = 0; q < 4; q++) {
                unsigned long long a2 =
                    *(const unsigned long long*)&As[k][ty * 8 + 2 * q];
                fma2(acc2[q][0], a2, bb[0]);
                fma2(acc2[q][1], a2, bb[1]);
                fma2(acc2[q][2], a2, bb[2]);
                fma2(acc2[q][3], a2, bb[3]);
            }
        }
        __syncthreads();
    }
    float4 bias = ((const float4*)b2)[tx];
    #pragma unroll
    for (int q = 0; q < 4; q++) {
        float lo[4], hi[4];
        #pragma unroll
        for (int c = 0; c < 4; c++) unpack2(acc2[q][c], lo[c], hi[c]);
        int r0 = row0 + ty * 8 + 2 * q;
        if (r0 < N_NODES) {
            float4 v = make_float4(fmaxf(lo[0] + bias.x, 0.f),
                                   fmaxf(lo[1] + bias.y, 0.f),
                                   fmaxf(lo[2] + bias.z, 0.f),
                                   fmaxf(lo[3] + bias.w, 0.f));
            ((float4*)g_bufB)[r0 * 32 + tx] = v;
        }
        if (r0 + 1 < N_NODES) {
            float4 v = make_float4(fmaxf(hi[0] + bias.x, 0.f),
                                   fmaxf(hi[1] + bias.y, 0.f),
                                   fmaxf(hi[2] + bias.z, 0.f),
                                   fmaxf(hi[3] + bias.w, 0.f));
            ((float4*)g_bufB)[(r0 + 1) * 32 + tx] = v;
        }
    }
}

// pool sums from bufB (batch sorted -> local accumulation); also graph counts.
// 32 nodes per block -> short serial chains.
__global__ void k_pool(const void* batch) {
    int tid = threadIdx.x;
    int start = blockIdx.x * 32;
    int end = min(start + 32, N_NODES);
    if (start >= N_NODES) return;
    int is64 = g_is64;
    int curg = ld_idx(batch, start, is64);
    float acc = 0.f;
    int runlen = 0;
    for (int n = start; n < end; n++) {
        int g = ld_idx(batch, n, is64);
        if (g != curg) {
            atomicAdd(&g_pool[curg * 128 + tid], acc);
            if (tid == 0) atomicAdd(&g_gcnt[curg], runlen);
            acc = 0.f; runlen = 0;
            curg = g;
        }
        acc += g_bufB[n * 128 + tid];
        runlen++;
    }
    atomicAdd(&g_pool[curg * 128 + tid], acc);
    if (tid == 0) atomicAdd(&g_gcnt[curg], runlen);
}

__global__ void k_final(const float* __restrict__ Wfc,
                        const float* __restrict__ bfc,
                        float* __restrict__ out) {
    int tid = threadIdx.x;   // 1024 = 64*16
    int g = tid >> 4;
    int o = tid & 15;
    float c = (float)max(g_gcnt[g], 1);
    float s = 0.f;
    #pragma unroll 8
    for (int k = 0; k < 128; k++)
        s = fmaf(g_pool[g * 128 + k], Wfc[k * 16 + o], s);
    out[tid] = s / c + bfc[o];
}

// ---------------- launch ----------------------------------------------------
extern "C" void kernel_launch(void* const* d_in, const int* in_sizes, int n_in,
                              void* d_out, int out_size) {
    const float* x   = (const float*)d_in[0];
    const void*  ei  = d_in[1];
    const void*  bat = d_in[2];
    const float* W1  = (const float*)d_in[3];
    const float* b1  = (const float*)d_in[4];
    const float* W2  = (const float*)d_in[5];
    const float* b2  = (const float*)d_in[6];
    const float* Wfc = (const float*)d_in[7];
    const float* bfc = (const float*)d_in[8];
    float* out = (float*)d_out;

    k_init<<<(N_NODES + 255) / 256, 256>>>();                 // 1
    k_build<<<(N_EDGES / 2 + 255) / 256, 256>>>(ei);          // 2
    k_dinvxs<<<(N_NODES * 16 + 255) / 256, 256>>>(x);         // 3
    k_aggx<<<(N_NODES * 32 + 255) / 256, 256>>>();            // 4  <- ncu slot
    k_gemm1<<<(N_NODES + 31) / 32, 128>>>(W1, b1);            // 5
    k_aggh<<<(N_NODES + 7) / 8, 256>>>();                     // 6
    k_gemm2<<<(N_NODES + 63) / 64, 256>>>(W2, b2);            // 7
    k_pool<<<(N_NODES + 31) / 32, 128>>>(bat);                // 8
    k_final<<<1, 1024>>>(Wfc, bfc, out);                      // 9
}